// round 16
// baseline (speedup 1.0000x reference)
#include <cuda_runtime.h>

// B=32, L=1024, D=64.
// Algebraic collapse (verified R1-R15, rel_err ~1.4e-7):
//   out[b,0,:] = sum_l x[b,l,:] / 1024 ;  out[b,1:,:] = 0.
//   W1,b1,W2,b2,timestamp are dead inputs.
//
// R16: minimal-launch shape. Grid = 64 CTAs x 1024 threads, homogeneous:
//   block (b,h) : - 8 batched LDG.128 (its 128B column slice, all 1024 rows)
//                 - 8 fire-and-forget STG.128 zeros in the LDG shadow
//                   (1/64 of out, skipping each batch's row 0)
//                 - reduce, exclusively write out[b,0, h*32:h*32+32)
// 64*1024*8 = 524288 f4 stores covers the whole output; row-0 slices are
// written only by their owning block. No atomics, no fences, 1 barrier.

#define NBLOCKS  64
#define NTHREADS 1024

#define F4_PER_BATCH 16384u   // 1024 rows * 16 float4
#define F4_PER_ROW   16u
#define N_F4_TOTAL   (32u * F4_PER_BATCH)   // 524288

__device__ __forceinline__ void f4add(float4& a, const float4& b) {
    a.x += b.x; a.y += b.y; a.z += b.z; a.w += b.w;
}

__device__ __forceinline__ float4 f4shfl_down(float4 v, int delta) {
    v.x = __shfl_down_sync(0xffffffffu, v.x, delta);
    v.y = __shfl_down_sync(0xffffffffu, v.y, delta);
    v.z = __shfl_down_sync(0xffffffffu, v.z, delta);
    v.w = __shfl_down_sync(0xffffffffu, v.w, delta);
    return v;
}

__global__ void __launch_bounds__(NTHREADS, 1) um_fused_kernel(
    const float4* __restrict__ x4, float4* __restrict__ out4)
{
    const int bid = blockIdx.x;
    const int tid = threadIdx.x;

    // ---- read side: (b, h) owns the 128B slice h of batch b ---------------
    const int b  = bid >> 1;
    const int h  = bid & 1;
    const int c  = tid & 7;        // float4 column within 128B slice
    const int lg = tid >> 3;       // 0..127: row group

    const float4* base = x4 + (size_t)b * F4_PER_BATCH
                            + (size_t)lg * F4_PER_ROW + h * 8 + c;

    // 8 independent LDG.128 from one base + immediate offsets (MLP=8)
    float4 v[8];
    #pragma unroll
    for (int j = 0; j < 8; ++j)
        v[j] = base[(size_t)j * 128u * F4_PER_ROW];   // +128 rows each

    // ---- store side, issued while loads are in flight ---------------------
    // thread covers f4 indices gt + k*65536, k=0..7 (exactly all of out),
    // skipping each batch's row 0 (written exclusively below).
    {
        const float4 z = make_float4(0.f, 0.f, 0.f, 0.f);
        const unsigned gt = (unsigned)bid * NTHREADS + (unsigned)tid; // 0..65535
        #pragma unroll
        for (unsigned k = 0; k < 8; ++k) {
            unsigned i = gt + k * 65536u;
            if ((i & (F4_PER_BATCH - 1u)) >= F4_PER_ROW)
                out4[i] = z;
        }
    }

    // ---- consume loads -----------------------------------------------------
    float4 a0 = v[0], a1 = v[1], a2 = v[2], a3 = v[3];
    f4add(a0, v[4]); f4add(a1, v[5]); f4add(a2, v[6]); f4add(a3, v[7]);
    f4add(a0, a1); f4add(a2, a3); f4add(a0, a2);

    // warp reduce: lanes sharing (lane & 7) share a column
    f4add(a0, f4shfl_down(a0, 16));
    f4add(a0, f4shfl_down(a0, 8));

    __shared__ float4 sm[32][8];   // [warp][col]
    const int lane = tid & 31;
    const int wid  = tid >> 5;
    if (lane < 8) sm[wid][lane] = a0;
    __syncthreads();

    // single-warp batched final reduce
    if (wid == 0) {
        const int cc = lane & 7;
        const int g  = lane >> 3;
        float4 u0 = sm[g*8+0][cc], u1 = sm[g*8+1][cc];
        float4 u2 = sm[g*8+2][cc], u3 = sm[g*8+3][cc];
        float4 u4 = sm[g*8+4][cc], u5 = sm[g*8+5][cc];
        float4 u6 = sm[g*8+6][cc], u7 = sm[g*8+7][cc];
        f4add(u0, u1); f4add(u2, u3); f4add(u4, u5); f4add(u6, u7);
        f4add(u0, u2); f4add(u4, u6); f4add(u0, u4);

        f4add(u0, f4shfl_down(u0, 16));
        f4add(u0, f4shfl_down(u0, 8));

        if (lane < 8) {
            const float inv = 1.0f / 1024.0f;
            u0.x *= inv; u0.y *= inv; u0.z *= inv; u0.w *= inv;
            out4[(size_t)b * F4_PER_BATCH + h * 8 + lane] = u0;
        }
    }
}

extern "C" void kernel_launch(void* const* d_in, const int* in_sizes, int n_in,
                              void* d_out, int out_size) {
    const float4* x4 = (const float4*)d_in[0];   // user_embedding [32,1024,64]
    float4* out4 = (float4*)d_out;               // [32,1024,64]
    um_fused_kernel<<<NBLOCKS, NTHREADS>>>(x4, out4);
}

// round 17
// speedup vs baseline: 1.0037x; 1.0037x over previous
#include <cuda_runtime.h>

// B=32, L=1024, D=64.
// Algebraic collapse (verified R1-R15, rel_err ~1.4e-7):
//   out[b,0,:] = sum_l x[b,l,:] / 1024 ;  out[b,1:,:] = 0.
//   W1,b1,W2,b2,timestamp are dead inputs.
//
// R16: minimal-launch shape. Grid = 64 CTAs x 1024 threads, homogeneous:
//   block (b,h) : - 8 batched LDG.128 (its 128B column slice, all 1024 rows)
//                 - 8 fire-and-forget STG.128 zeros in the LDG shadow
//                   (1/64 of out, skipping each batch's row 0)
//                 - reduce, exclusively write out[b,0, h*32:h*32+32)
// 64*1024*8 = 524288 f4 stores covers the whole output; row-0 slices are
// written only by their owning block. No atomics, no fences, 1 barrier.

#define NBLOCKS  64
#define NTHREADS 1024

#define F4_PER_BATCH 16384u   // 1024 rows * 16 float4
#define F4_PER_ROW   16u
#define N_F4_TOTAL   (32u * F4_PER_BATCH)   // 524288

__device__ __forceinline__ void f4add(float4& a, const float4& b) {
    a.x += b.x; a.y += b.y; a.z += b.z; a.w += b.w;
}

__device__ __forceinline__ float4 f4shfl_down(float4 v, int delta) {
    v.x = __shfl_down_sync(0xffffffffu, v.x, delta);
    v.y = __shfl_down_sync(0xffffffffu, v.y, delta);
    v.z = __shfl_down_sync(0xffffffffu, v.z, delta);
    v.w = __shfl_down_sync(0xffffffffu, v.w, delta);
    return v;
}

__global__ void __launch_bounds__(NTHREADS, 1) um_fused_kernel(
    const float4* __restrict__ x4, float4* __restrict__ out4)
{
    const int bid = blockIdx.x;
    const int tid = threadIdx.x;

    // ---- read side: (b, h) owns the 128B slice h of batch b ---------------
    const int b  = bid >> 1;
    const int h  = bid & 1;
    const int c  = tid & 7;        // float4 column within 128B slice
    const int lg = tid >> 3;       // 0..127: row group

    const float4* base = x4 + (size_t)b * F4_PER_BATCH
                            + (size_t)lg * F4_PER_ROW + h * 8 + c;

    // 8 independent LDG.128 from one base + immediate offsets (MLP=8)
    float4 v[8];
    #pragma unroll
    for (int j = 0; j < 8; ++j)
        v[j] = base[(size_t)j * 128u * F4_PER_ROW];   // +128 rows each

    // ---- store side, issued while loads are in flight ---------------------
    // thread covers f4 indices gt + k*65536, k=0..7 (exactly all of out),
    // skipping each batch's row 0 (written exclusively below).
    {
        const float4 z = make_float4(0.f, 0.f, 0.f, 0.f);
        const unsigned gt = (unsigned)bid * NTHREADS + (unsigned)tid; // 0..65535
        #pragma unroll
        for (unsigned k = 0; k < 8; ++k) {
            unsigned i = gt + k * 65536u;
            if ((i & (F4_PER_BATCH - 1u)) >= F4_PER_ROW)
                out4[i] = z;
        }
    }

    // ---- consume loads -----------------------------------------------------
    float4 a0 = v[0], a1 = v[1], a2 = v[2], a3 = v[3];
    f4add(a0, v[4]); f4add(a1, v[5]); f4add(a2, v[6]); f4add(a3, v[7]);
    f4add(a0, a1); f4add(a2, a3); f4add(a0, a2);

    // warp reduce: lanes sharing (lane & 7) share a column
    f4add(a0, f4shfl_down(a0, 16));
    f4add(a0, f4shfl_down(a0, 8));

    __shared__ float4 sm[32][8];   // [warp][col]
    const int lane = tid & 31;
    const int wid  = tid >> 5;
    if (lane < 8) sm[wid][lane] = a0;
    __syncthreads();

    // single-warp batched final reduce
    if (wid == 0) {
        const int cc = lane & 7;
        const int g  = lane >> 3;
        float4 u0 = sm[g*8+0][cc], u1 = sm[g*8+1][cc];
        float4 u2 = sm[g*8+2][cc], u3 = sm[g*8+3][cc];
        float4 u4 = sm[g*8+4][cc], u5 = sm[g*8+5][cc];
        float4 u6 = sm[g*8+6][cc], u7 = sm[g*8+7][cc];
        f4add(u0, u1); f4add(u2, u3); f4add(u4, u5); f4add(u6, u7);
        f4add(u0, u2); f4add(u4, u6); f4add(u0, u4);

        f4add(u0, f4shfl_down(u0, 16));
        f4add(u0, f4shfl_down(u0, 8));

        if (lane < 8) {
            const float inv = 1.0f / 1024.0f;
            u0.x *= inv; u0.y *= inv; u0.z *= inv; u0.w *= inv;
            out4[(size_t)b * F4_PER_BATCH + h * 8 + lane] = u0;
        }
    }
}

extern "C" void kernel_launch(void* const* d_in, const int* in_sizes, int n_in,
                              void* d_out, int out_size) {
    const float4* x4 = (const float4*)d_in[0];   // user_embedding [32,1024,64]
    float4* out4 = (float4*)d_out;               // [32,1024,64]
    um_fused_kernel<<<NBLOCKS, NTHREADS>>>(x4, out4);
}